// round 14
// baseline (speedup 1.0000x reference)
#include <cuda_runtime.h>
#include <cuda_fp16.h>
#include <cstdint>

// GRU seq2seq forecaster — fused tensor-core recurrence, 2 CTAs/SM anti-phase.
//  K0: xsplit — x -> fp16 PERMUTED 64B records (frag-major u32 layout).
//  K1: CTA = 16 rows, 256 thr, 8 warps; warp wn owns 8 units x 3 gates (24 cols,
//      30 MMA/step). Grid 256 -> 2 independent CTAs/SM whose MMA and epilogue
//      phases slide against each other. Arithmetic identical to R12.

#define B_    4096
#define TIN   168
#define C_    32
#define H_    64
#define TOUT  24

typedef uint32_t u32;
typedef unsigned long long u64;

__device__ u32 g_xs[(size_t)TIN * B_ * 16];   // 44 MB fp16 permuted x records

__device__ __forceinline__ float tanhap(float a) {
    float r; asm("tanh.approx.f32 %0, %1;" : "=f"(r) : "f"(a)); return r;
}
__device__ __forceinline__ float fsig(float a) {           // sigma(a)=0.5+0.5*tanh(a/2)
    return fmaf(tanhap(0.5f * a), 0.5f, 0.5f);
}
__device__ __forceinline__ u32 packh2(float a, float b) {  // low fp16 = a, high = b
    u32 d; asm("cvt.rn.f16x2.f32 %0, %1, %2;" : "=r"(d) : "f"(b), "f"(a)); return d;
}
__device__ __forceinline__ void splith2(float a, float b, u32& hi2, u32& lo2) {
    hi2 = packh2(a, b);
    __half2 hv = *reinterpret_cast<const __half2*>(&hi2);
    lo2 = packh2(a - __low2float(hv), b - __high2float(hv));
}
__device__ __forceinline__ void MMA(float acc[4], u32 a0, u32 a1, u32 a2, u32 a3,
                                    u32 b0, u32 b1) {
    asm volatile(
        "mma.sync.aligned.m16n8k16.row.col.f32.f16.f16.f32 "
        "{%0,%1,%2,%3}, {%4,%5,%6,%7}, {%8,%9}, {%0,%1,%2,%3};"
        : "+f"(acc[0]), "+f"(acc[1]), "+f"(acc[2]), "+f"(acc[3])
        : "r"(a0), "r"(a1), "r"(a2), "r"(a3), "r"(b0), "r"(b1));
}
__device__ __forceinline__ u32 smem_u32(const void* p) {
    u32 a;
    asm("{ .reg .u64 t; cvta.to.shared.u64 t, %1; cvt.u32.u64 %0, t; }" : "=r"(a) : "l"(p));
    return a;
}
__device__ __forceinline__ void cp16(u32 daddr, const void* gsrc) {
    asm volatile("cp.async.cg.shared.global [%0], [%1], 16;"
                 :: "r"(daddr), "l"(gsrc) : "memory");
}

// ============================ kernel 0: x pre-split (fp16, permuted) ============================
__global__ __launch_bounds__(256)
void xsplit_kernel(const float* __restrict__ x)
{
    const int p = blockIdx.x * 256 + threadIdx.x;      // t*B + b
    const int t = p >> 12, b = p & (B_ - 1);
    const float4* s4 = reinterpret_cast<const float4*>(x + ((size_t)b * TIN + t) * C_);
    float4 v[8];
#pragma unroll
    for (int i = 0; i < 8; i++) v[i] = s4[i];
    u32 s[16];
#pragma unroll
    for (int i = 0; i < 8; i++) {
        s[2 * i]     = packh2(v[i].x, v[i].y);
        s[2 * i + 1] = packh2(v[i].z, v[i].w);
    }
    uint4* dst = reinterpret_cast<uint4*>(g_xs + (size_t)p * 16);
#pragma unroll
    for (int j4 = 0; j4 < 4; j4++)
        dst[j4] = make_uint4(s[j4], s[4 + j4], s[8 + j4], s[12 + j4]);
}

// ============================ kernel 1: fused recurrence ============================
#define HSu 36     // sH row stride (u32): 32 data + 4 pad
#define PSu 16
#define XSu 16

#define OFF_H   0                         // [2 par][16][HSu] u32 = 4608
#define OFF_P   4608                      // [2 par][16][PSu] u32 = 2048
#define OFF_X   6656                      // [2 buf][16][XSu] u32 = 2048
#define OFF_WF  8704                      // [8 wn][3 nt][2 ks][32] uint2 = 12288
#define OFF_PF  20992                     // [4][4 ks][32] uint4 = 8192
#define SM_TOTAL 29184

#define AFRAG_FROM(v0a, v0b, v1a, v1b, a0, a1, a2, a3)                     \
    a0[0]=(v0a).x; a2[0]=(v0a).y; a1[0]=(v1a).x; a3[0]=(v1a).y;            \
    a0[1]=(v0a).z; a2[1]=(v0a).w; a1[1]=(v1a).z; a3[1]=(v1a).w;            \
    a0[2]=(v0b).x; a2[2]=(v0b).y; a1[2]=(v1b).x; a3[2]=(v1b).y;            \
    a0[3]=(v0b).z; a2[3]=(v0b).w; a1[3]=(v1b).z; a3[3]=(v1b).w;

__global__ __launch_bounds__(256, 2)
void gru_fused(const float* __restrict__ x,
               const float* __restrict__ eWih, const float* __restrict__ eWhh,
               const float* __restrict__ eBih, const float* __restrict__ eBhh,
               const float* __restrict__ dWih, const float* __restrict__ dWhh,
               const float* __restrict__ dBih, const float* __restrict__ dBhh,
               const float* __restrict__ pW,   const float* __restrict__ pB,
               float* __restrict__ out)
{
    extern __shared__ __align__(16) char smem[];
    u32* sHu       = reinterpret_cast<u32*>(smem + OFF_H);
    u32* sPu       = reinterpret_cast<u32*>(smem + OFF_P);
    const u32* sXu = reinterpret_cast<const u32*>(smem + OFF_X);
    uint2* sWf     = reinterpret_cast<uint2*>(smem + OFF_WF);
    uint4* sPf     = reinterpret_cast<uint4*>(smem + OFF_PF);
    const u32 smb = smem_u32(smem);

    const int tid  = threadIdx.x;
    const int wn   = tid >> 5;         // unit octet 0..7 (24 output cols: r,z,n of 8 units)
    const int lane = tid & 31;
    const int g  = lane >> 2;
    const int tg = lane & 3;
    const int R0 = g, R1 = g + 8;      // 16-row tile
    const int rowbase = blockIdx.x * 16;

    for (int i = tid; i < 2 * 16 * HSu; i += 256) sHu[i] = 0;

    // ---- stage encoder Wih frags (hi fp16 only), each warp its wn ----
#pragma unroll
    for (int nt = 0; nt < 3; nt++)
#pragma unroll
        for (int ks = 0; ks < 2; ks++) {
            const float* wr = eWih + (nt * 64 + 8 * wn + g) * 32 + ks * 16 + 2 * tg;
            sWf[((wn * 3 + nt) * 2 + ks) * 32 + lane] =
                make_uint2(packh2(wr[0], wr[1]), packh2(wr[8], wr[9]));
        }
    // ---- encoder Whh frags: hi + lo fp16 in registers (48 u32) ----
    u32 bh[3][4][2], bw[3][4][2];
#pragma unroll
    for (int nt = 0; nt < 3; nt++) {
        const float* row = eWhh + (nt * 64 + 8 * wn + g) * 64;
#pragma unroll
        for (int ks = 0; ks < 4; ks++) {
            const int k0 = ks * 16 + 2 * tg;
            splith2(row[k0],     row[k0 + 1], bh[nt][ks][0], bw[nt][ks][0]);
            splith2(row[k0 + 8], row[k0 + 9], bh[nt][ks][1], bw[nt][ks][1]);
        }
    }
    float ebr[2], ebz[2], eni[2], enh[2];
#pragma unroll
    for (int c = 0; c < 2; c++) {
        const int u = 8 * wn + 2 * tg + c;
        ebr[c] = eBih[u] + eBhh[u];
        ebz[c] = eBih[64 + u] + eBhh[64 + u];
        eni[c] = eBih[128 + u];
        enh[c] = eBhh[128 + u];
    }
    __syncthreads();

    if (tid < 64) {   // prologue: prefetch x tile t=0 (16 rows x 64B)
        const int row = tid >> 2, ch = tid & 3;
        const char* src = reinterpret_cast<const char*>(
            g_xs + ((size_t)(rowbase + row)) * 16) + ch * 16;
        cp16(smb + OFF_X + row * 64 + ch * 16, src);
        asm volatile("cp.async.commit_group;" ::: "memory");
    }

    float h[4];
#pragma unroll
    for (int e = 0; e < 4; e++) h[e] = 0.0f;
    int hp = 0;

    // ======================= encoder: 168 steps =======================
    for (int t = 0; t < TIN; t++) {
        asm volatile("cp.async.wait_group 0;" ::: "memory");
        __syncthreads();
        if (t + 1 < TIN && tid < 64) {
            const int row = tid >> 2, ch = tid & 3;
            const char* src = reinterpret_cast<const char*>(
                g_xs + ((size_t)(t + 1) * B_ + rowbase + row) * 16) + ch * 16;
            cp16(smb + OFF_X + ((t + 1) & 1) * 1024 + row * 64 + ch * 16, src);
            asm volatile("cp.async.commit_group;" ::: "memory");
        }

        const u32* hbu = sHu + hp * (16 * HSu);
        const uint4* h0p = reinterpret_cast<const uint4*>(hbu + R0 * HSu + tg * 8);
        const uint4* h1p = reinterpret_cast<const uint4*>(hbu + R1 * HSu + tg * 8);
        const uint4 v0a = h0p[0], v0b = h0p[1], v1a = h1p[0], v1b = h1p[1];
        u32 a0[4], a1[4], a2[4], a3[4];
        AFRAG_FROM(v0a, v0b, v1a, v1b, a0, a1, a2, a3);

        const u32* xb = sXu + (t & 1) * 256;
        const uint4 xv0 = *reinterpret_cast<const uint4*>(xb + R0 * XSu + tg * 4);
        const uint4 xv1 = *reinterpret_cast<const uint4*>(xb + R1 * XSu + tg * 4);
        u32 x0[2], x1[2], x2[2], x3[2];
        x0[0]=xv0.x; x2[0]=xv0.y; x0[1]=xv0.z; x2[1]=xv0.w;
        x1[0]=xv1.x; x3[0]=xv1.y; x1[1]=xv1.z; x3[1]=xv1.w;

        float accW[3][4], accP[4];
#pragma unroll
        for (int j = 0; j < 4; j++) {
            const int c = j & 1;
            accW[0][j] = ebr[c];
            accW[1][j] = ebz[c];
            accW[2][j] = enh[c];
            accP[j]    = eni[c];
        }
#pragma unroll
        for (int nt = 0; nt < 3; nt++) {
            float* A = accW[nt];
#pragma unroll
            for (int ks = 0; ks < 4; ks++)
                MMA(A, a0[ks], a1[ks], a2[ks], a3[ks], bh[nt][ks][0], bh[nt][ks][1]);
#pragma unroll
            for (int ks = 0; ks < 4; ks++)
                MMA(A, a0[ks], a1[ks], a2[ks], a3[ks], bw[nt][ks][0], bw[nt][ks][1]);
            float* T = (nt < 2) ? A : accP;
#pragma unroll
            for (int ks = 0; ks < 2; ks++) {
                const uint2 w = sWf[((wn * 3 + nt) * 2 + ks) * 32 + lane];
                MMA(T, x0[ks], x1[ks], x2[ks], x3[ks], w.x, w.y);
            }
        }

        u32* hwu = sHu + (hp ^ 1) * (16 * HSu);
#pragma unroll
        for (int rh = 0; rh < 2; rh++) {
#pragma unroll
            for (int c = 0; c < 2; c++) {
                const int j = 2 * rh + c, e = j;
                const float rg = fsig(accW[0][j]);
                const float zg = fsig(accW[1][j]);
                const float nn = tanhap(fmaf(rg, accW[2][j], accP[j]));
                h[e] = nn + zg * (h[e] - nn);
            }
            const int row = rh ? R1 : R0;
            hwu[row * HSu + tg * 8 + wn] = packh2(h[2 * rh], h[2 * rh + 1]);
        }
        hp ^= 1;
    }

    // ======================= decoder: 24 steps =======================
    __syncthreads();
#pragma unroll
    for (int nt = 0; nt < 3; nt++)   // restage decoder Wih
#pragma unroll
        for (int ks = 0; ks < 2; ks++) {
            const float* wr = dWih + (nt * 64 + 8 * wn + g) * 32 + ks * 16 + 2 * tg;
            sWf[((wn * 3 + nt) * 2 + ks) * 32 + lane] =
                make_uint2(packh2(wr[0], wr[1]), packh2(wr[8], wr[9]));
        }
    if (wn < 4) {                    // projection W frags (split hi/lo)
#pragma unroll
        for (int ks = 0; ks < 4; ks++) {
            const float* wr = pW + (8 * wn + g) * 64 + ks * 16 + 2 * tg;
            u32 h0, l0, h1, l1;
            splith2(wr[0], wr[1], h0, l0);
            splith2(wr[8], wr[9], h1, l1);
            sPf[(wn * 4 + ks) * 32 + lane] = make_uint4(h0, h1, l0, l1);
        }
    }
#pragma unroll
    for (int nt = 0; nt < 3; nt++) {   // decoder Whh frags
        const float* row = dWhh + (nt * 64 + 8 * wn + g) * 64;
#pragma unroll
        for (int ks = 0; ks < 4; ks++) {
            const int k0 = ks * 16 + 2 * tg;
            splith2(row[k0],     row[k0 + 1], bh[nt][ks][0], bw[nt][ks][0]);
            splith2(row[k0 + 8], row[k0 + 9], bh[nt][ks][1], bw[nt][ks][1]);
        }
    }
    float dbr[2], dbz[2], dni[2], dnh[2];
#pragma unroll
    for (int c = 0; c < 2; c++) {
        const int u = 8 * wn + 2 * tg + c;
        dbr[c] = dBih[u] + dBhh[u];
        dbz[c] = dBih[64 + u] + dBhh[64 + u];
        dni[c] = dBih[128 + u];
        dnh[c] = dBhh[128 + u];
    }
    const int pcol = 8 * wn + 2 * tg;           // valid for wn<4 (projection cols)
    const float pb0 = (wn < 4) ? pB[pcol] : 0.f;
    const float pb1 = (wn < 4) ? pB[pcol + 1] : 0.f;

    {   // prev_0 = x[:, TIN-1, :] — copy permuted records (one u32 per thread)
        const int row = tid >> 4, w = tid & 15;
        sPu[row * PSu + w] = g_xs[((size_t)(TIN - 1) * B_ + rowbase + row) * 16 + w];
    }
    __syncthreads();

    int pp = 0;
    for (int t = 0; t < TOUT; t++) {
        const u32* hbu = sHu + hp * (16 * HSu);
        const uint4* h0p = reinterpret_cast<const uint4*>(hbu + R0 * HSu + tg * 8);
        const uint4* h1p = reinterpret_cast<const uint4*>(hbu + R1 * HSu + tg * 8);
        const uint4 v0a = h0p[0], v0b = h0p[1], v1a = h1p[0], v1b = h1p[1];
        u32 a0[4], a1[4], a2[4], a3[4];
        AFRAG_FROM(v0a, v0b, v1a, v1b, a0, a1, a2, a3);

        const u32* pbu = sPu + pp * (16 * PSu);
        const uint4 pv0 = *reinterpret_cast<const uint4*>(pbu + R0 * PSu + tg * 4);
        const uint4 pv1 = *reinterpret_cast<const uint4*>(pbu + R1 * PSu + tg * 4);
        u32 x0[2], x1[2], x2[2], x3[2];
        x0[0]=pv0.x; x2[0]=pv0.y; x0[1]=pv0.z; x2[1]=pv0.w;
        x1[0]=pv1.x; x3[0]=pv1.y; x1[1]=pv1.z; x3[1]=pv1.w;

        float accW[3][4], accP[4];
#pragma unroll
        for (int j = 0; j < 4; j++) {
            const int c = j & 1;
            accW[0][j] = dbr[c];
            accW[1][j] = dbz[c];
            accW[2][j] = dnh[c];
            accP[j]    = dni[c];
        }
#pragma unroll
        for (int nt = 0; nt < 3; nt++) {
            float* A = accW[nt];
#pragma unroll
            for (int ks = 0; ks < 4; ks++)
                MMA(A, a0[ks], a1[ks], a2[ks], a3[ks], bh[nt][ks][0], bh[nt][ks][1]);
#pragma unroll
            for (int ks = 0; ks < 4; ks++)
                MMA(A, a0[ks], a1[ks], a2[ks], a3[ks], bw[nt][ks][0], bw[nt][ks][1]);
            float* T = (nt < 2) ? A : accP;
#pragma unroll
            for (int ks = 0; ks < 2; ks++) {
                const uint2 w = sWf[((wn * 3 + nt) * 2 + ks) * 32 + lane];
                MMA(T, x0[ks], x1[ks], x2[ks], x3[ks], w.x, w.y);
            }
        }

        u32* hwu = sHu + (hp ^ 1) * (16 * HSu);
#pragma unroll
        for (int rh = 0; rh < 2; rh++) {
#pragma unroll
            for (int c = 0; c < 2; c++) {
                const int j = 2 * rh + c;
                const float rg = fsig(accW[0][j]);
                const float zg = fsig(accW[1][j]);
                const float nn = tanhap(fmaf(rg, accW[2][j], accP[j]));
                h[j] = nn + zg * (h[j] - nn);
            }
            const int row = rh ? R1 : R0;
            hwu[row * HSu + tg * 8 + wn] = packh2(h[2 * rh], h[2 * rh + 1]);
        }
        __syncthreads();

        // projection from NEW h (warps wn<4 -> output cols 8wn..8wn+7)
        if (wn < 4) {
            const u32* hnu = sHu + (hp ^ 1) * (16 * HSu);
            const uint4* n0p = reinterpret_cast<const uint4*>(hnu + R0 * HSu + tg * 8);
            const uint4* n1p = reinterpret_cast<const uint4*>(hnu + R1 * HSu + tg * 8);
            const uint4 w0a = n0p[0], w0b = n0p[1], w1a = n1p[0], w1b = n1p[1];
            u32 n0[4], n1[4], n2[4], n3[4];
            AFRAG_FROM(w0a, w0b, w1a, w1b, n0, n1, n2, n3);
            float pacc[4] = {0.f, 0.f, 0.f, 0.f};
#pragma unroll
            for (int ks = 0; ks < 4; ks++) {
                const uint4 w = sPf[(wn * 4 + ks) * 32 + lane];
                MMA(pacc, n0[ks], n1[ks], n2[ks], n3[ks], w.x, w.y);
                MMA(pacc, n0[ks], n1[ks], n2[ks], n3[ks], w.z, w.w);
            }
            const float p00 = pacc[0] + pb0, p01 = pacc[1] + pb1;
            const float p10 = pacc[2] + pb0, p11 = pacc[3] + pb1;
            *reinterpret_cast<float2*>(&out[((size_t)(rowbase + R0) * TOUT + t) * C_ + pcol]) = make_float2(p00, p01);
            *reinterpret_cast<float2*>(&out[((size_t)(rowbase + R1) * TOUT + t) * C_ + pcol]) = make_float2(p10, p11);
            u32* pnu = sPu + (pp ^ 1) * (16 * PSu);
            pnu[R0 * PSu + tg * 4 + wn] = packh2(p00, p01);
            pnu[R1 * PSu + tg * 4 + wn] = packh2(p10, p11);
        }
        __syncthreads();
        hp ^= 1; pp ^= 1;
    }
}

// ============================ launch ============================
extern "C" void kernel_launch(void* const* d_in, const int* in_sizes, int n_in,
                              void* d_out, int out_size)
{
    (void)in_sizes; (void)n_in; (void)out_size;
    const float* x    = (const float*)d_in[0];
    const float* eWih = (const float*)d_in[1];
    const float* eWhh = (const float*)d_in[2];
    const float* eBih = (const float*)d_in[3];
    const float* eBhh = (const float*)d_in[4];
    const float* dWih = (const float*)d_in[5];
    const float* dWhh = (const float*)d_in[6];
    const float* dBih = (const float*)d_in[7];
    const float* dBhh = (const float*)d_in[8];
    const float* pW   = (const float*)d_in[9];
    const float* pB   = (const float*)d_in[10];
    float* out = (float*)d_out;

    xsplit_kernel<<<(TIN * B_) / 256, 256>>>(x);

    cudaFuncSetAttribute(gru_fused,
                         cudaFuncAttributeMaxDynamicSharedMemorySize, SM_TOTAL);
    gru_fused<<<B_ / 16, 256, SM_TOTAL>>>(
        x, eWih, eWhh, eBih, eBhh, dWih, dWhh, dBih, dBhh, pW, pB, out);
}